// round 1
// baseline (speedup 1.0000x reference)
#include <cuda_runtime.h>

#define TILE  32
#define HALO  5
#define IN_W  42              // TILE + 2*HALO
#define IMG   512
#define BATCH 32

// Gaussian window (ws=11, sigma=1.5), normalized — matches jnp float32 chain
#define GW0 0.00102838f
#define GW1 0.00759876f
#define GW2 0.03600077f
#define GW3 0.10936069f
#define GW4 0.21300554f
#define GW5 0.26601173f

__device__ double g_accum;

__global__ void ssim_init_kernel() { g_accum = 0.0; }

__global__ __launch_bounds__(256, 4)
void ssim_main_kernel(const float* __restrict__ pred,
                      const float* __restrict__ targ)
{
    __shared__ float sP[IN_W * IN_W];
    __shared__ float sT[IN_W * IN_W];
    __shared__ float h1[IN_W * TILE];
    __shared__ float h2[IN_W * TILE];
    __shared__ float h3[IN_W * TILE];
    __shared__ float h4[IN_W * TILE];
    __shared__ float h5[IN_W * TILE];
    __shared__ float red[8];

    const float GW[11] = {GW0, GW1, GW2, GW3, GW4, GW5, GW4, GW3, GW2, GW1, GW0};

    const int tid = threadIdx.x;                 // 0..255
    const int n  = blockIdx.z;
    const int x0 = blockIdx.x * TILE - HALO;
    const int y0 = blockIdx.y * TILE - HALO;
    const float* __restrict__ pbase = pred + (size_t)n * IMG * IMG;
    const float* __restrict__ tbase = targ + (size_t)n * IMG * IMG;

    // ---- Phase 1: load 42x42 halo tiles (zero-pad OOB, matches conv zero padding)
    #pragma unroll
    for (int idx = tid; idx < IN_W * IN_W; idx += 256) {
        int r = idx / IN_W, c = idx - r * IN_W;
        int gy = y0 + r, gx = x0 + c;
        float p = 0.f, t = 0.f;
        if (gx >= 0 && gx < IMG && gy >= 0 && gy < IMG) {
            p = __ldg(pbase + gy * IMG + gx);
            t = __ldg(tbase + gy * IMG + gx);
        }
        sP[idx] = p;
        sT[idx] = t;
    }
    __syncthreads();

    // ---- Phase 2: horizontal 11-tap blur of 5 fields over 42 rows x 32 cols
    #pragma unroll
    for (int idx = tid; idx < IN_W * TILE; idx += 256) {
        int c = idx & (TILE - 1);
        int r = idx >> 5;
        const float* rp = sP + r * IN_W + c;
        const float* rt = sT + r * IN_W + c;
        float s1 = 0.f, s2 = 0.f, s3 = 0.f, s4 = 0.f, s5 = 0.f;
        #pragma unroll
        for (int k = 0; k < 11; k++) {
            float p = rp[k];
            float t = rt[k];
            s1 = fmaf(GW[k], p,     s1);
            s2 = fmaf(GW[k], t,     s2);
            s3 = fmaf(GW[k], p * p, s3);
            s4 = fmaf(GW[k], t * t, s4);
            s5 = fmaf(GW[k], p * t, s5);
        }
        h1[idx] = s1; h2[idx] = s2; h3[idx] = s3; h4[idx] = s4; h5[idx] = s5;
    }
    __syncthreads();

    // ---- Phase 3: vertical blur + SSIM map; each thread does 4 output rows
    const int tx  = tid & 31;
    const int tyb = tid >> 5;                    // 0..7
    float acc = 0.f;
    #pragma unroll
    for (int i = 0; i < 4; i++) {
        int ro = tyb + i * 8;                    // output row 0..31
        float m1 = 0.f, m2 = 0.f, e11 = 0.f, e22 = 0.f, e12 = 0.f;
        #pragma unroll
        for (int k = 0; k < 11; k++) {
            int off = (ro + k) * TILE + tx;
            m1  = fmaf(GW[k], h1[off], m1);
            m2  = fmaf(GW[k], h2[off], m2);
            e11 = fmaf(GW[k], h3[off], e11);
            e22 = fmaf(GW[k], h4[off], e22);
            e12 = fmaf(GW[k], h5[off], e12);
        }
        float mu1s = m1 * m1;
        float mu2s = m2 * m2;
        float mu12 = m1 * m2;
        float v1   = e11 - mu1s;                 // sigma1_sq
        float v2   = e22 - mu2s;                 // sigma2_sq
        float cv   = e12 - mu12;                 // sigma12
        const float C1 = 1e-4f;                  // 0.01^2
        const float C2 = 9e-4f;                  // 0.03^2
        float num = (2.f * mu12 + C1) * (2.f * cv + C2);
        float den = (mu1s + mu2s + C1) * (v1 + v2 + C2);
        acc += __fdividef(num, den);
    }

    // ---- Phase 4: block reduction -> double atomic
    #pragma unroll
    for (int o = 16; o > 0; o >>= 1)
        acc += __shfl_xor_sync(0xffffffffu, acc, o);
    if ((tid & 31) == 0) red[tid >> 5] = acc;
    __syncthreads();
    if (tid < 8) {
        float v = red[tid];
        #pragma unroll
        for (int o = 4; o > 0; o >>= 1)
            v += __shfl_xor_sync(0xffu, v, o);
        if (tid == 0) atomicAdd(&g_accum, (double)v);
    }
}

__global__ void ssim_final_kernel(float* __restrict__ out)
{
    const double inv_n = 1.0 / ((double)BATCH * IMG * IMG);
    out[0] = (float)(1.0 - g_accum * inv_n);
}

extern "C" void kernel_launch(void* const* d_in, const int* in_sizes, int n_in,
                              void* d_out, int out_size)
{
    const float* pred = (const float*)d_in[0];
    const float* targ = (const float*)d_in[1];
    float* out = (float*)d_out;

    ssim_init_kernel<<<1, 1>>>();
    dim3 grid(IMG / TILE, IMG / TILE, BATCH);    // 16 x 16 x 32
    ssim_main_kernel<<<grid, 256>>>(pred, targ);
    ssim_final_kernel<<<1, 1>>>(out);
}

// round 2
// speedup vs baseline: 1.1378x; 1.1378x over previous
#include <cuda_runtime.h>

#define TILE  32
#define HALO  5
#define NR    42              // rows/cols of halo tile (TILE + 2*HALO)
#define PADW  44              // padded smem row width (multiple of 4 for float4)
#define IMG   512
#define BATCH 32
#define NBLK  (16*16*32)      // 8192 blocks

__device__ float g_part[NBLK];

// Gaussian window (ws=11, sigma=1.5), normalized — matches jnp float32 chain
__device__ __forceinline__ float gw(int k) {
    const float G[11] = {0.00102838f, 0.00759876f, 0.03600077f, 0.10936069f,
                         0.21300554f, 0.26601173f, 0.21300554f, 0.10936069f,
                         0.03600077f, 0.00759876f, 0.00102838f};
    return G[k];
}

// 11-tap blur of 4 consecutive outputs from a 14-element register window
__device__ __forceinline__ float4 blur4(const float* __restrict__ x) {
    float4 s;
    s.x = 0.f; s.y = 0.f; s.z = 0.f; s.w = 0.f;
    #pragma unroll
    for (int k = 0; k < 11; k++) {
        float g = gw(k);
        s.x = fmaf(g, x[k + 0], s.x);
        s.y = fmaf(g, x[k + 1], s.y);
        s.z = fmaf(g, x[k + 2], s.z);
        s.w = fmaf(g, x[k + 3], s.w);
    }
    return s;
}

__global__ __launch_bounds__(256, 3)
void ssim_main_kernel(const float* __restrict__ pred,
                      const float* __restrict__ targ)
{
    __shared__ __align__(16) float sP[NR * PADW];
    __shared__ __align__(16) float sT[NR * PADW];
    __shared__ __align__(16) float h1[NR * TILE];
    __shared__ __align__(16) float h2[NR * TILE];
    __shared__ __align__(16) float h3[NR * TILE];
    __shared__ __align__(16) float h4[NR * TILE];
    __shared__ __align__(16) float h5[NR * TILE];
    __shared__ float red[8];

    const int tid = threadIdx.x;                 // 0..255
    const int n  = blockIdx.z;
    const int x0 = blockIdx.x * TILE - HALO;
    const int y0 = blockIdx.y * TILE - HALO;
    const float* __restrict__ pbase = pred + (size_t)n * IMG * IMG;
    const float* __restrict__ tbase = targ + (size_t)n * IMG * IMG;

    // ---- Phase 1: load 42x42 halo tiles into padded smem (zero-pad OOB)
    for (int idx = tid; idx < NR * NR; idx += 256) {
        int r = idx / NR, c = idx - r * NR;
        int gy = y0 + r, gx = x0 + c;
        float p = 0.f, t = 0.f;
        if ((unsigned)gx < IMG && (unsigned)gy < IMG) {
            p = __ldg(pbase + gy * IMG + gx);
            t = __ldg(tbase + gy * IMG + gx);
        }
        sP[r * PADW + c] = p;
        sT[r * PADW + c] = t;
    }
    __syncthreads();

    // ---- Phase 2: horizontal blur, 4 consecutive cols per item via float4
    // items: 42 rows x 8 col-groups = 336
    for (int it = tid; it < NR * 8; it += 256) {
        int r = it >> 3;
        int q = it & 7;
        const float4* vp = (const float4*)(sP + r * PADW + q * 4);
        const float4* vt = (const float4*)(sT + r * PADW + q * 4);
        float4 A0 = vp[0], A1 = vp[1], A2 = vp[2], A3 = vp[3];
        float4 B0 = vt[0], B1 = vt[1], B2 = vt[2], B3 = vt[3];
        float xp[16] = {A0.x, A0.y, A0.z, A0.w, A1.x, A1.y, A1.z, A1.w,
                        A2.x, A2.y, A2.z, A2.w, A3.x, A3.y, A3.z, A3.w};
        float xt[16] = {B0.x, B0.y, B0.z, B0.w, B1.x, B1.y, B1.z, B1.w,
                        B2.x, B2.y, B2.z, B2.w, B3.x, B3.y, B3.z, B3.w};
        int ho = r * TILE + q * 4;

        *(float4*)(h1 + ho) = blur4(xp);
        {
            float pp[14];
            #pragma unroll
            for (int j = 0; j < 14; j++) pp[j] = xp[j] * xp[j];
            *(float4*)(h3 + ho) = blur4(pp);
        }
        *(float4*)(h2 + ho) = blur4(xt);
        {
            float tt[14];
            #pragma unroll
            for (int j = 0; j < 14; j++) tt[j] = xt[j] * xt[j];
            *(float4*)(h4 + ho) = blur4(tt);
        }
        {
            float pt[14];
            #pragma unroll
            for (int j = 0; j < 14; j++) pt[j] = xp[j] * xt[j];
            *(float4*)(h5 + ho) = blur4(pt);
        }
    }
    __syncthreads();

    // ---- Phase 3: vertical blur + SSIM, 4 consecutive rows per thread
    const int tx = tid & 31;
    const int ty = tid >> 5;                     // 0..7
    const int rbase = ty * 4;                    // output rows rbase..rbase+3

    float m1[4], m2[4], e11[4], e22[4], e12[4];
    #pragma unroll
    for (int i = 0; i < 4; i++) { m1[i]=0.f; m2[i]=0.f; e11[i]=0.f; e22[i]=0.f; e12[i]=0.f; }

    #pragma unroll
    for (int j = 0; j < 14; j++) {
        int off = (rbase + j) * TILE + tx;
        float v1 = h1[off], v2 = h2[off], v3 = h3[off], v4 = h4[off], v5 = h5[off];
        #pragma unroll
        for (int i = 0; i < 4; i++) {
            int k = j - i;
            if (k >= 0 && k < 11) {
                float g = gw(k);
                m1[i]  = fmaf(g, v1, m1[i]);
                m2[i]  = fmaf(g, v2, m2[i]);
                e11[i] = fmaf(g, v3, e11[i]);
                e22[i] = fmaf(g, v4, e22[i]);
                e12[i] = fmaf(g, v5, e12[i]);
            }
        }
    }

    float acc = 0.f;
    #pragma unroll
    for (int i = 0; i < 4; i++) {
        float mu1s = m1[i] * m1[i];
        float mu2s = m2[i] * m2[i];
        float mu12 = m1[i] * m2[i];
        float v1   = e11[i] - mu1s;              // sigma1_sq
        float v2   = e22[i] - mu2s;              // sigma2_sq
        float cv   = e12[i] - mu12;              // sigma12
        const float C1 = 1e-4f;                  // 0.01^2
        const float C2 = 9e-4f;                  // 0.03^2
        float num = (2.f * mu12 + C1) * (2.f * cv + C2);
        float den = (mu1s + mu2s + C1) * (v1 + v2 + C2);
        acc += __fdividef(num, den);
    }

    // ---- Phase 4: block reduction -> per-block partial (no init needed)
    #pragma unroll
    for (int o = 16; o > 0; o >>= 1)
        acc += __shfl_xor_sync(0xffffffffu, acc, o);
    if ((tid & 31) == 0) red[tid >> 5] = acc;
    __syncthreads();
    if (tid < 8) {
        float v = red[tid];
        #pragma unroll
        for (int o = 4; o > 0; o >>= 1)
            v += __shfl_xor_sync(0xffu, v, o);
        if (tid == 0) {
            int bid = (blockIdx.z * gridDim.y + blockIdx.y) * gridDim.x + blockIdx.x;
            g_part[bid] = v;
        }
    }
}

__global__ __launch_bounds__(1024)
void ssim_final_kernel(float* __restrict__ out)
{
    __shared__ double sd[32];
    int tid = threadIdx.x;
    double v = 0.0;
    #pragma unroll
    for (int i = 0; i < NBLK / 1024; i++)
        v += (double)g_part[tid + i * 1024];
    #pragma unroll
    for (int o = 16; o > 0; o >>= 1)
        v += __shfl_xor_sync(0xffffffffu, v, o);
    if ((tid & 31) == 0) sd[tid >> 5] = v;
    __syncthreads();
    if (tid < 32) {
        double w = sd[tid];
        #pragma unroll
        for (int o = 16; o > 0; o >>= 1)
            w += __shfl_xor_sync(0xffffffffu, w, o);
        if (tid == 0)
            out[0] = (float)(1.0 - w / ((double)BATCH * IMG * IMG));
    }
}

extern "C" void kernel_launch(void* const* d_in, const int* in_sizes, int n_in,
                              void* d_out, int out_size)
{
    const float* pred = (const float*)d_in[0];
    const float* targ = (const float*)d_in[1];
    float* out = (float*)d_out;

    dim3 grid(IMG / TILE, IMG / TILE, BATCH);    // 16 x 16 x 32
    ssim_main_kernel<<<grid, 256>>>(pred, targ);
    ssim_final_kernel<<<1, 1024>>>(out);
}